// round 15
// baseline (speedup 1.0000x reference)
#include <cuda_runtime.h>
#include <cuda_fp16.h>
#include <cstdint>

#define TILE_Z 32
#define NTH    256
#define NITER  4

#define C000f 0.7071067811865476f
#define C110f 0.4082482904638631f
#define C011f 0.7071067811865476f
#define C101f 0.7071067811865476f

// B fragments, fp16-packed, 0.125-scaled, vector-friendly layout:
//   idx = ((wsel*4+kk)*2+nh)*256 + gID*32 + tig*8 + nt   (uint2 each)
//   value: pair for n = nh*64 + nt*8 + gID, K0 = kk*16 + 2*tig
__device__ uint2 g_wt[4096];
// Folded tp_w: [0]=C000*wA, [64]=C110*wD, [128]=C011*wB, [192]=C101*wC
__device__ float g_tpw[256];

__device__ __forceinline__ uint32_t smem_u32(const void* p) {
    uint32_t a;
    asm("{ .reg .u64 t; cvta.to.shared.u64 t, %1; cvt.u32.u64 %0, t; }" : "=r"(a) : "l"(p));
    return a;
}
__device__ __forceinline__ uint32_t h2u(float a, float b) {
    __half2 h = __floats2half2_rn(a, b);
    return *reinterpret_cast<uint32_t*>(&h);
}
__device__ __forceinline__ void ldsm_x4(uint32_t* r, uint32_t addr) {
    asm volatile("ldmatrix.sync.aligned.m8n8.x4.shared.b16 {%0,%1,%2,%3}, [%4];"
        : "=r"(r[0]), "=r"(r[1]), "=r"(r[2]), "=r"(r[3]) : "r"(addr));
}
__device__ __forceinline__ void mma_f16(float* c, const uint32_t* a, uint32_t bx, uint32_t by) {
    asm volatile("mma.sync.aligned.m16n8k16.row.col.f32.f16.f16.f32 "
        "{%0,%1,%2,%3}, {%4,%5,%6,%7}, {%8,%9}, {%0,%1,%2,%3};"
        : "+f"(c[0]), "+f"(c[1]), "+f"(c[2]), "+f"(c[3])
        : "r"(a[0]), "r"(a[1]), "r"(a[2]), "r"(a[3]), "r"(bx), "r"(by));
}

// ---------------- pack kernel ----------------
__global__ void pack_kernel(const float* __restrict__ tp_w,
                            const float* __restrict__ w0,
                            const float* __restrict__ w1) {
    int t = blockIdx.x * blockDim.x + threadIdx.x;
    if (t < 4096) {
        int tig  = t & 3;
        int n    = (t >> 2) & 127;
        int kk   = (t >> 9) & 3;
        int wsel = t >> 11;
        const float* w = wsel ? w1 : w0;
        int K0 = kk * 16 + 2 * tig;
        uint2 v;
        v.x = h2u(w[K0 * 128 + n] * 0.125f,       w[(K0 + 1) * 128 + n] * 0.125f);
        v.y = h2u(w[(K0 + 8) * 128 + n] * 0.125f, w[(K0 + 9) * 128 + n] * 0.125f);
        int nh  = n >> 6;
        int nt  = (n >> 3) & 7;
        int gID = n & 7;
        g_wt[(((wsel * 4 + kk) * 2 + nh) * 8 + gID) * 32 + tig * 8 + nt] = v;
    } else if (t < 4096 + 64) {
        int u = t - 4096;
        g_tpw[u]       = C000f * tp_w[u];
        g_tpw[64 + u]  = C110f * tp_w[192 + u];
        g_tpw[128 + u] = C011f * tp_w[64 + u];
        g_tpw[192 + u] = C101f * tp_w[128 + u];
    }
}

// ---------------- main kernel ----------------
// Per-CTA dynamic smem:
//   A double buffer: 2 x half[128 rows][72] (18432 B each) -> 36864
//   stage single buffer (interleaved cols): float[32][396]  -> 50688
// Total 87552 B -> 2 CTAs/SM = 175104 B; ~53 KB L1D (B = 32 KB stays cached).
#define A_ROW_H   72
#define A_BYTES   (128 * A_ROW_H * 2)        // 18432
#define STG_STRIDE 396
#define STG_OFF   (2 * A_BYTES)              // 36864
#define DSM_BYTES (STG_OFF + 32 * STG_STRIDE * 4)  // 87552

// Phase 1: compute mids for one 32-row tile, pack half2, STS into A buffer.
__device__ __forceinline__ void phase1(__half* A, const float* __restrict__ x,
                                       const float* __restrict__ y, int z0,
                                       const float* s_tpw, int tid) {
    #pragma unroll
    for (int it = 0; it < (TILE_Z * 16) / NTH; it++) {
        int task = tid + NTH * it;        // 0..511
        int z = task >> 4;
        int q = task & 15;
        const float* xp = x + (size_t)(z0 + z) * 256;
        float4 X0 = *(const float4*)(xp + 4 * q);
        const float4* xq = (const float4*)(xp + 64 + 12 * q);
        float4 P0 = xq[0], P1 = xq[1], P2 = xq[2];
        float4 Y  = *(const float4*)(y + (size_t)(z0 + z) * 4);
        float y0v = Y.x, ya = Y.y, yb = Y.z, yc = Y.w;
        float4 tA = *(const float4*)(s_tpw + 4 * q);
        float4 tD = *(const float4*)(s_tpw + 64 + 4 * q);
        float4 tB = *(const float4*)(s_tpw + 128 + 4 * q);
        float4 tC = *(const float4*)(s_tpw + 192 + 4 * q);

        float x0a[4] = {X0.x, X0.y, X0.z, X0.w};
        float xaa[4] = {P0.x, P0.w, P1.z, P2.y};
        float xba[4] = {P0.y, P1.x, P1.w, P2.z};
        float xca[4] = {P0.z, P1.y, P2.x, P2.w};
        float tAa[4] = {tA.x, tA.y, tA.z, tA.w};
        float tDa[4] = {tD.x, tD.y, tD.z, tD.w};
        float tBa[4] = {tB.x, tB.y, tB.z, tB.w};
        float tCa[4] = {tC.x, tC.y, tC.z, tC.w};

        float m0[4], ma[4], mb[4], mc[4];
        #pragma unroll
        for (int j = 0; j < 4; j++) {
            m0[j] = tAa[j] * x0a[j] * y0v
                  + tDa[j] * (xaa[j] * ya + xba[j] * yb + xca[j] * yc);
            float tb = tBa[j] * x0a[j];
            float tc = tCa[j] * y0v;
            ma[j] = tb * ya + tc * xaa[j];
            mb[j] = tb * yb + tc * xba[j];
            mc[j] = tb * yc + tc * xca[j];
        }
        uint2 H0 = make_uint2(h2u(m0[0], m0[1]), h2u(m0[2], m0[3]));
        uint2 HA = make_uint2(h2u(ma[0], ma[1]), h2u(ma[2], ma[3]));
        uint2 HB = make_uint2(h2u(mb[0], mb[1]), h2u(mb[2], mb[3]));
        uint2 HC = make_uint2(h2u(mc[0], mc[1]), h2u(mc[2], mc[3]));

        __half* rp = A + (size_t)z * A_ROW_H + 4 * q;
        *(uint2*)(rp)                 = H0;   // rows  0..31  : ch0
        *(uint2*)(rp + 32 * A_ROW_H)  = HA;   // rows 32..63  : ch1
        *(uint2*)(rp + 64 * A_ROW_H)  = HB;   // rows 64..95  : ch2
        *(uint2*)(rp + 96 * A_ROW_H)  = HC;   // rows 96..127 : ch3
    }
}

// ch0 (cols 0..127): direct, sector-aligned STG for a 16-row chunk (one m-tile).
__device__ __forceinline__ void ch0_store16(float* __restrict__ out, int zbase,
                                            const float a[8][4],
                                            int nh, int gID, int tig) {
    float* o0 = out + (size_t)(zbase + gID) * 512 + nh * 64 + 2 * tig;
    float* o1 = o0 + 8 * 512;
    #pragma unroll
    for (int nt = 0; nt < 8; nt++) {
        *(float2*)(o0 + nt * 8) = make_float2(a[nt][0], a[nt][1]);
        *(float2*)(o1 + nt * 8) = make_float2(a[nt][2], a[nt][3]);
    }
}

// Interleaved channels: stage col = 3n + k3 (out col 128+3n+k3), 16-row chunk.
__device__ __forceinline__ void stage_write16i(float* stage, const float a[8][4],
                                               int k3, int nh, int gID, int tig) {
    float* r0 = stage + (size_t)gID * STG_STRIDE;
    float* r1 = r0 + 8 * STG_STRIDE;
    #pragma unroll
    for (int nt = 0; nt < 8; nt++) {
        int n = nh * 64 + nt * 8 + 2 * tig;
        int o = 3 * n + k3;
        r0[o]     = a[nt][0];
        r0[o + 3] = a[nt][1];
        r1[o]     = a[nt][2];
        r1[o + 3] = a[nt][3];
    }
}

__global__ void __launch_bounds__(NTH, 2)
tpmm_kernel(const float* __restrict__ x, const float* __restrict__ y,
            float* __restrict__ out) {
    extern __shared__ __align__(128) char dsm[];
    __shared__ float s_tpw[256];

    const int tid = threadIdx.x;
    if (tid < 256) s_tpw[tid] = g_tpw[tid];

    const int warp = tid >> 5;
    const int lane = tid & 31;
    const int gID  = lane >> 2;
    const int tig  = lane & 3;
    const int mq   = warp >> 1;   // 0..3 channel
    const int nh   = warp & 1;    // 0..1 N half

    float* stage = (float*)(dsm + STG_OFF);   // 32 rows x 396
    // B base (vector layout): wsel*2048 + nh*256 + gID*32 + tig*8 (uint2 units).
    const uint4* wb = (const uint4*)(g_wt + (mq ? 2048 : 0) + nh * 256 + gID * 32 + tig * 8);

    const int t0z = blockIdx.x * (NITER * TILE_Z);

    __syncthreads();   // s_tpw visible
    phase1((__half*)dsm, x, y, t0z, s_tpw, tid);

    #pragma unroll
    for (int t = 0; t < NITER; t++) {
        const int z0 = t0z + t * TILE_Z;
        // Barrier 1: A[t&1] visible; stage fully read by prev tile's copy-out.
        __syncthreads();

        const uint32_t a_base = smem_u32(dsm) + (uint32_t)((t & 1) * A_BYTES)
            + (uint32_t)((mq * 32 + ((lane >> 3) & 1) * 8 + (lane & 7)) * (A_ROW_H * 2))
            + (uint32_t)((lane >> 4) * 16);

        float acc[2][8][4];
        #pragma unroll
        for (int mt = 0; mt < 2; mt++)
            #pragma unroll
            for (int nt = 0; nt < 8; nt++)
                #pragma unroll
                for (int j = 0; j < 4; j++) acc[mt][nt][j] = 0.f;

        #pragma unroll
        for (int kk = 0; kk < 4; kk++) {
            uint32_t afr[2][4];
            #pragma unroll
            for (int mt = 0; mt < 2; mt++)
                ldsm_x4(afr[mt], a_base + (uint32_t)(mt * 16 * A_ROW_H * 2 + kk * 32));
            uint4 bv[4];   // each uint4 = two nt fragments
            #pragma unroll
            for (int p = 0; p < 4; p++)
                bv[p] = wb[kk * 256 + p];   // kk stride = 512 uint2 = 256 uint4  (FIXED)
            #pragma unroll
            for (int mt = 0; mt < 2; mt++) {
                #pragma unroll
                for (int p = 0; p < 4; p++) {
                    mma_f16(acc[mt][2 * p],     afr[mt], bv[p].x, bv[p].y);
                    mma_f16(acc[mt][2 * p + 1], afr[mt], bv[p].z, bv[p].w);
                }
            }
        }

        // ---- Epilogue: ch0 direct; interleaved staged (both m-tiles), 1 sync. ----
        if (mq == 0) {
            ch0_store16(out, z0,      acc[0], nh, gID, tig);
            ch0_store16(out, z0 + 16, acc[1], nh, gID, tig);
        } else {
            stage_write16i(stage,                   acc[0], mq - 1, nh, gID, tig);
            stage_write16i(stage + 16 * STG_STRIDE, acc[1], mq - 1, nh, gID, tig);
        }
        // Barrier 2: stage staged; all ldsm reads of A[t&1] complete.
        __syncthreads();

        // Copy-out 32 rows x 384 interleaved cols (12 float4 per thread).
        #pragma unroll
        for (int j = 0; j < 12; j++) {
            int i = tid + NTH * j;
            int s = i / 96;
            int c = (i % 96) << 2;
            float4 v = *(const float4*)(stage + (size_t)s * STG_STRIDE + c);
            *(float4*)(out + (size_t)(z0 + s) * 512 + 128 + c) = v;
        }

        // Overlapped phase 1 for next tile (writes the other A buffer).
        if (t + 1 < NITER)
            phase1((__half*)(dsm + ((t + 1) & 1) * A_BYTES), x, y, z0 + TILE_Z, s_tpw, tid);
    }
}

extern "C" void kernel_launch(void* const* d_in, const int* in_sizes, int n_in,
                              void* d_out, int out_size) {
    const float* x    = (const float*)d_in[0];
    const float* y    = (const float*)d_in[1];
    const float* tp_w = (const float*)d_in[2];
    const float* w0   = (const float*)d_in[3];
    const float* w1   = (const float*)d_in[4];
    float* out        = (float*)d_out;

    int Z = in_sizes[0] / 256;

    pack_kernel<<<(4096 + 64 + 255) / 256, 256>>>(tp_w, w0, w1);

    cudaFuncSetAttribute(tpmm_kernel,
                         cudaFuncAttributeMaxDynamicSharedMemorySize, DSM_BYTES);
    tpmm_kernel<<<Z / (TILE_Z * NITER), NTH, DSM_BYTES>>>(x, y, out);
}